// round 13
// baseline (speedup 1.0000x reference)
#include <cuda_runtime.h>
#include <cuda_fp16.h>
#include <cstdint>

// ============================================================================
// sLSTM cell, B=4096, D=4096 on sm_103a (legacy mma path).
// G = [x | h^T] (4096 x 8192) @ Wcat (8192 x 16384), gate columns PERMUTED so
// each warp's 64-col slice = 16 features x all 4 gates:
//   pcol(g, d) = (d>>4)*64 + g*16 + (d&15)
// -> sLSTM cell computed in the GEMM epilogue from registers (no G scratch).
// SINGLE fp16 pass (fp32 accum); calibrated error ~4.1e-4 < 1e-3.
// R13: 6 slots x 16KB (BK=32), macro-steps of 3 stages with ONE barrier per
// macro (86 barriers vs 128): macro m computes half P=m&1, fills the other
// half (batched commit; CP_WAIT(0) at macro start, group committed ~1300cy
// earlier). Barrier-free stage boundaries let next-stage ldsm overlap with
// draining MMAs. BK=32 addressing + 64B-row swizzle = validated R5 scheme.
// R12's skew (falsified) and GROUP=16 (neutral) reverted.
// ============================================================================

#define BDIM 4096
#define DDIM 4096
#define KDIM 8192
#define NDIM 16384

#define BM 128
#define BN 128
#define BK 32
#define NSTG 256                   // KDIM / BK
#define TIL16 8192                 // 128 rows x 32 cols x 2B per operand tile
#define STG   16384                // stage = A tile + B tile
#define SMEMB (6 * STG)            // 98304 -> 2 CTAs/SM

// -------------------- scratch (module-scope, allowed) -----------------------
__device__ __align__(256) __half g_A[(size_t)BDIM * KDIM];
__device__ __align__(256) __half g_B[(size_t)NDIM * KDIM];

// -------------------- PTX helpers -------------------------------------------
__device__ __forceinline__ uint32_t smem_u32(const void* p) {
    uint32_t a;
    asm("{ .reg .u64 t; cvta.to.shared.u64 t, %1; cvt.u32.u64 %0, t; }"
        : "=r"(a) : "l"(p));
    return a;
}
__device__ __forceinline__ void cp_async16(uint32_t dst, const void* src) {
    asm volatile("cp.async.cg.shared.global [%0], [%1], 16;" :: "r"(dst), "l"(src) : "memory");
}
#define CP_COMMIT() asm volatile("cp.async.commit_group;" ::: "memory")
#define CP_WAIT(N)  asm volatile("cp.async.wait_group %0;" :: "n"(N) : "memory")

__device__ __forceinline__ void ldsm4(uint32_t& r0, uint32_t& r1, uint32_t& r2, uint32_t& r3,
                                      uint32_t addr) {
    asm volatile("ldmatrix.sync.aligned.m8n8.x4.shared.b16 {%0,%1,%2,%3}, [%4];"
                 : "=r"(r0), "=r"(r1), "=r"(r2), "=r"(r3) : "r"(addr));
}
__device__ __forceinline__ void mma16816(float* c, const uint32_t* a, const uint32_t* b) {
    asm volatile(
        "mma.sync.aligned.m16n8k16.row.col.f32.f16.f16.f32 "
        "{%0,%1,%2,%3}, {%4,%5,%6,%7}, {%8,%9}, {%0,%1,%2,%3};"
        : "+f"(c[0]), "+f"(c[1]), "+f"(c[2]), "+f"(c[3])
        : "r"(a[0]), "r"(a[1]), "r"(a[2]), "r"(a[3]), "r"(b[0]), "r"(b[1]));
}

// swizzled byte offset within one [128][32] fp16 tile (64B rows, 4 chunks).
// conflict-free for cp.async writes and ldmatrix 8-row reads (validated R5).
__device__ __forceinline__ uint32_t sw64(uint32_t row, uint32_t c16) {
    return row * 64u + (((c16 ^ (row >> 1)) & 3u) << 4);
}

// -------------------- prep kernels ------------------------------------------
__global__ void __launch_bounds__(256) prep_x(const float* __restrict__ x) {
    size_t gid = (size_t)blockIdx.x * 256 + threadIdx.x;   // 4,194,304 float4s
    size_t i4 = gid * 4;
    int b = (int)(i4 >> 12), k = (int)(i4 & 4095);
    float4 v = reinterpret_cast<const float4*>(x)[gid];
    __half2* dst = reinterpret_cast<__half2*>(&g_A[(size_t)b * KDIM + k]);
    dst[0] = __floats2half2_rn(v.x, v.y);
    dst[1] = __floats2half2_rn(v.z, v.w);
}

// h is (D, B) fp32; g_A[b][4096 + r] = h[r][b].
__global__ void __launch_bounds__(256) prep_h(const float* __restrict__ h) {
    __shared__ float t[64][65];
    const int l = threadIdx.x;
    int b0 = blockIdx.x * 64, r0 = blockIdx.y * 64;
#pragma unroll
    for (int it = 0; it < 4; it++) {
        int idx = l + 256 * it;
        int row = idx >> 4;
        int c4 = idx & 15;
        float4 v = *reinterpret_cast<const float4*>(&h[(size_t)(r0 + row) * BDIM + b0 + c4 * 4]);
        t[row][c4 * 4 + 0] = v.x;
        t[row][c4 * 4 + 1] = v.y;
        t[row][c4 * 4 + 2] = v.z;
        t[row][c4 * 4 + 3] = v.w;
    }
    __syncthreads();
#pragma unroll
    for (int it = 0; it < 8; it++) {
        int idx = l + 256 * it;
        int brow = idx >> 5;
        int cp = idx & 31;
        __half2 v = __floats2half2_rn(t[2 * cp][brow], t[2 * cp + 1][brow]);
        size_t o = (size_t)(b0 + brow) * KDIM + 4096 + r0 + 2 * cp;
        *reinterpret_cast<__half2*>(&g_A[o]) = v;
    }
}

// 64x64 tile transpose; writes are 128B-coalesced half2 rows.
// Output row uses the gate-interleaved permutation pcol(g,d).
__global__ void __launch_bounds__(256) prep_w(
    const float* w0, const float* w1, const float* w2, const float* w3,
    const float* u0, const float* u1, const float* u2, const float* u3) {
    __shared__ float t[64][65];
    const int l = threadIdx.x;
    int z = blockIdx.z;
    const float* arr[8] = {w0, w1, w2, w3, u0, u1, u2, u3};
    const float* src = arr[z];
    int gate = z & 3, khalf = z >> 2;
    int d0 = blockIdx.x * 64, k0 = blockIdx.y * 64;
#pragma unroll
    for (int it = 0; it < 4; it++) {
        int idx = l + 256 * it;
        int row = idx >> 4;
        int c4 = idx & 15;
        float4 v = *reinterpret_cast<const float4*>(&src[(size_t)(k0 + row) * DDIM + d0 + c4 * 4]);
        t[row][c4 * 4 + 0] = v.x;
        t[row][c4 * 4 + 1] = v.y;
        t[row][c4 * 4 + 2] = v.z;
        t[row][c4 * 4 + 3] = v.w;
    }
    __syncthreads();
#pragma unroll
    for (int it = 0; it < 8; it++) {
        int idx = l + 256 * it;
        int drow = idx >> 5;
        int cp = idx & 31;
        __half2 v = __floats2half2_rn(t[2 * cp][drow], t[2 * cp + 1][drow]);
        int d = d0 + drow;
        int prow = (d >> 4) * 64 + gate * 16 + (d & 15);   // gate interleave
        size_t o = (size_t)prow * KDIM + khalf * 4096 + k0 + 2 * cp;
        *reinterpret_cast<__half2*>(&g_B[o]) = v;
    }
}

// -------------------- GEMM + fused cell kernel -------------------------------
// fill ONE 16KB stage: 4 cp.async/thread, immediate smem offsets.
// Thread covers A rows (tid>>2), (tid>>2)+64 and same for B; off(q+256) =
// off(q) + 4096 (row+64 preserves swizzle phase).
struct FillPtrs { const char* pa; const char* pb; };
__device__ __forceinline__ void fill_stage(uint32_t sdst, FillPtrs& fp) {
    const size_t R64 = (size_t)64 * KDIM * 2;   // 64 rows in bytes
    cp_async16(sdst + 0,     fp.pa);
    cp_async16(sdst + 4096,  fp.pa + R64);
    cp_async16(sdst + 8192,  fp.pb);
    cp_async16(sdst + 12288, fp.pb + R64);
    fp.pa += BK * 2;
    fp.pb += BK * 2;
}

// one k16 block of one stage slot: 6 ldsm + 16 MMA.
template<int SLOT, int KK>
__device__ __forceinline__ void kkblock(
    const uint32_t (&aA)[2][2], const uint32_t (&aB)[4][2], float (&acc)[2][8][4]) {
    uint32_t a[2][4];
    uint32_t b[8][2];
#pragma unroll
    for (int f = 0; f < 2; f++)
        ldsm4(a[f][0], a[f][1], a[f][2], a[f][3], aA[f][KK] + SLOT * STG);
#pragma unroll
    for (int p = 0; p < 4; p++) {
        uint32_t r0, r1, r2, r3;
        ldsm4(r0, r1, r2, r3, aB[p][KK] + SLOT * STG);
        b[p * 2 + 0][0] = r0; b[p * 2 + 0][1] = r2;
        b[p * 2 + 1][0] = r1; b[p * 2 + 1][1] = r3;
    }
#pragma unroll
    for (int f = 0; f < 2; f++)
#pragma unroll
        for (int n = 0; n < 8; n++)
            mma16816(acc[f][n], a[f], b[n]);
}

// one macro step: barrier once, compute 3 stages in half P, fill FILLN stages
// of the other half (spread under tensor backpressure, single commit).
template<int P, int FILLN>
__device__ __forceinline__ void mstep(
    uint32_t sb, uint32_t offT, FillPtrs& fp,
    const uint32_t (&aA)[2][2], const uint32_t (&aB)[4][2], float (&acc)[2][8][4]) {
    constexpr int CB = P * 3;           // compute slots CB..CB+2
    constexpr int FB = (1 - P) * 3;     // fill slots FB..FB+2
    CP_WAIT(0);
    __syncthreads();

    kkblock<CB + 0, 0>(aA, aB, acc);
    if (FILLN >= 1) fill_stage(sb + (FB + 0) * STG + offT, fp);
    if (FILLN == 1) CP_COMMIT();
    kkblock<CB + 0, 1>(aA, aB, acc);
    if (FILLN >= 2) fill_stage(sb + (FB + 1) * STG + offT, fp);
    kkblock<CB + 1, 0>(aA, aB, acc);
    if (FILLN >= 3) { fill_stage(sb + (FB + 2) * STG + offT, fp); CP_COMMIT(); }
    kkblock<CB + 1, 1>(aA, aB, acc);
    kkblock<CB + 2, 0>(aA, aB, acc);
    kkblock<CB + 2, 1>(aA, aB, acc);
}

__device__ __forceinline__ float cell1(float gi, float gf, float go, float gc,
                                       float cv, float mv, float nv,
                                       float& c_new, float& m_new, float& n_new) {
    m_new = fmaxf(gf + mv, gi);
    float i_p = expf(gi - m_new);
    float f_p = expf(gf);                 // faithful: +m_new - m_new cancels
    float o_t = 1.0f / (1.0f + expf(-go));
    float z_t = tanhf(gc);
    c_new = f_p * cv + i_p * z_t;
    n_new = f_p * nv + i_p;
    return o_t * (c_new / n_new);
}

__global__ void __launch_bounds__(256, 2) slstm_gemm(
    const float* __restrict__ cin, const float* __restrict__ min_,
    const float* __restrict__ nin,
    const float* __restrict__ bi, const float* __restrict__ bf,
    const float* __restrict__ bo, const float* __restrict__ bc,
    float* __restrict__ out) {
    extern __shared__ char smem[];
    uint32_t sb = smem_u32(smem);
    const int tid = threadIdx.x;
    const int wid = tid >> 5;
    const int lane = tid & 31;
    const int wm = wid >> 1;            // 0..3  (M warp, 32 rows)
    const int wn = wid & 1;             // 0..1  (N warp, 64 cols)

    // supertile rasterization for L2 reuse
    const int grid_m = BDIM / BM, grid_n = NDIM / BN;   // 32, 128
    const int GROUP = 8;
    int pid = blockIdx.x;
    int npg = GROUP * grid_n;
    int first_m = (pid / npg) * GROUP;
    int gs = min(grid_m - first_m, GROUP);
    int pig = pid % npg;
    int m0 = (first_m + (pig % gs)) * BM;
    int n0 = (pig / gs) * BN;

    // fill-side precompute: thread's swizzled offset within a stage + ptrs
    const int frow = tid >> 2;          // 0..63
    const int fc = tid & 3;             // 16B chunk 0..3
    const uint32_t offT = sw64(frow, fc);
    FillPtrs fp;
    fp.pa = (const char*)&g_A[(size_t)(m0 + frow) * KDIM] + fc * 16;
    fp.pb = (const char*)&g_B[(size_t)(n0 + frow) * KDIM] + fc * 16;

    // prologue: fill stages 0,1,2 (slots 0..2), one commit group
    fill_stage(sb + 0 * STG + offT, fp);
    fill_stage(sb + 1 * STG + offT, fp);
    fill_stage(sb + 2 * STG + offT, fp);
    CP_COMMIT();

    float acc[2][8][4];
#pragma unroll
    for (int f = 0; f < 2; f++)
#pragma unroll
        for (int n = 0; n < 8; n++)
#pragma unroll
            for (int v = 0; v < 4; v++) acc[f][n][v] = 0.0f;

    const int g = lane >> 3, lr = lane & 7;

    // hoisted swizzled ldmatrix addresses for slot 0, kk=0,1 (R5 mapping).
    uint32_t aA[2][2], aB[4][2];
#pragma unroll
    for (int f = 0; f < 2; f++)
#pragma unroll
        for (int kk = 0; kk < 2; kk++)
            aA[f][kk] = sb +
                        sw64(wm * 32 + f * 16 + lr + (g & 1) * 8, kk * 2 + (g >> 1));
#pragma unroll
    for (int p = 0; p < 4; p++)
#pragma unroll
        for (int kk = 0; kk < 2; kk++)
            aB[p][kk] = sb + TIL16 +
                        sw64(wn * 64 + p * 16 + lr + (g & 1) * 8, kk * 2 + (g >> 1));

    // macros 0..83: 42 x (even, odd); each computes 3 stages, fills 3 ahead.
    for (int mm = 0; mm < 42; mm++) {
        mstep<0, 3>(sb, offT, fp, aA, aB, acc);
        mstep<1, 3>(sb, offT, fp, aA, aB, acc);
    }
    // macro 84: computes stages 252..254 (slots 0..2), fills stage 255 (slot 3)
    mstep<0, 1>(sb, offT, fp, aA, aB, acc);
    // tail: stage 255 in slot 3
    CP_WAIT(0);
    __syncthreads();
    kkblock<3, 0>(aA, aB, acc);
    kkblock<3, 1>(aA, aB, acc);

    // ---------------- fused cell epilogue ----------------
    // Warp's 64 pcols = 16 features x 4 gates: gate g' at n-blocks 2g'+b,
    // feature d = dbase + b*8 + (lane&3)*2 (+0,+1).
    const size_t BD = (size_t)BDIM * DDIM;
    const int dbase = (n0 >> 2) + wn * 16;
    const int dth = dbase + (lane & 3) * 2;

    float2 bi2[2], bf2[2], bo2[2], bc2[2];
#pragma unroll
    for (int b = 0; b < 2; b++) {
        int d = dth + b * 8;
        bi2[b] = *reinterpret_cast<const float2*>(bi + d);
        bf2[b] = *reinterpret_cast<const float2*>(bf + d);
        bo2[b] = *reinterpret_cast<const float2*>(bo + d);
        bc2[b] = *reinterpret_cast<const float2*>(bc + d);
    }

    const size_t obase = (size_t)(m0 + wm * 32 + (lane >> 2)) * DDIM + dth;
#pragma unroll
    for (int f = 0; f < 2; f++) {
#pragma unroll
        for (int rr = 0; rr < 2; rr++) {        // rows +0, +8 within the frag
#pragma unroll
            for (int b = 0; b < 2; b++) {
                size_t o = obase + (size_t)(f * 16 + rr * 8) * DDIM + b * 8;
                float2 cv = *reinterpret_cast<const float2*>(cin + o);
                float2 mv = *reinterpret_cast<const float2*>(min_ + o);
                float2 nv = *reinterpret_cast<const float2*>(nin + o);

                float2 h2, c2, m2, n2;
                {
                    float gi = acc[f][0 + b][rr * 2 + 0] + bi2[b].x;
                    float gf = acc[f][2 + b][rr * 2 + 0] + bf2[b].x;
                    float go = acc[f][4 + b][rr * 2 + 0] + bo2[b].x;
                    float gc = acc[f][6 + b][rr * 2 + 0] + bc2[b].x;
                    h2.x = cell1(gi, gf, go, gc, cv.x, mv.x, nv.x, c2.x, m2.x, n2.x);
                }
                {
                    float gi = acc[f][0 + b][rr * 2 + 1] + bi2[b].y;
                    float gf = acc[f][2 + b][rr * 2 + 1] + bf2[b].y;
                    float go = acc[f][4 + b][rr * 2 + 1] + bo2[b].y;
                    float gc = acc[f][6 + b][rr * 2 + 1] + bc2[b].y;
                    h2.y = cell1(gi, gf, go, gc, cv.y, mv.y, nv.y, c2.y, m2.y, n2.y);
                }
                *reinterpret_cast<float2*>(out + 0 * BD + o) = h2;
                *reinterpret_cast<float2*>(out + 1 * BD + o) = c2;
                *reinterpret_cast<float2*>(out + 2 * BD + o) = m2;
                *reinterpret_cast<float2*>(out + 3 * BD + o) = n2;
            }
        }
    }
}

// -------------------- launcher ----------------------------------------------
extern "C" void kernel_launch(void* const* d_in, const int* in_sizes, int n_in,
                              void* d_out, int out_size) {
    (void)in_sizes; (void)n_in; (void)out_size;
    const float* x  = (const float*)d_in[0];
    const float* h  = (const float*)d_in[1];
    const float* c  = (const float*)d_in[2];
    const float* m  = (const float*)d_in[3];
    const float* n  = (const float*)d_in[4];
    const float* wi = (const float*)d_in[5];
    const float* wf = (const float*)d_in[6];
    const float* wo = (const float*)d_in[7];
    const float* wc = (const float*)d_in[8];
    const float* ui = (const float*)d_in[9];
    const float* uf = (const float*)d_in[10];
    const float* uo = (const float*)d_in[11];
    const float* uc = (const float*)d_in[12];
    const float* bi = (const float*)d_in[13];
    const float* bf = (const float*)d_in[14];
    const float* bo = (const float*)d_in[15];
    const float* bc = (const float*)d_in[16];

    cudaFuncSetAttribute(slstm_gemm, cudaFuncAttributeMaxDynamicSharedMemorySize, SMEMB);

    prep_x<<<16384, 256>>>(x);
    prep_h<<<dim3(64, 64), 256>>>(h);
    prep_w<<<dim3(64, 64, 8), 256>>>(wi, wf, wo, wc, ui, uf, uo, uc);
    slstm_gemm<<<4096, 256, SMEMB>>>(c, m, n, bi, bf, bo, bc, (float*)d_out);
}

// round 14
// speedup vs baseline: 1.5546x; 1.5546x over previous
#include <cuda_runtime.h>
#include <cuda_fp16.h>
#include <cstdint>

// ============================================================================
// sLSTM cell, B=4096, D=4096 on sm_103a (legacy mma path).
// G = [x | h^T] (4096 x 8192) @ Wcat (8192 x 16384), gate columns PERMUTED so
// each warp's 64-col slice = 16 features x all 4 gates:
//   pcol(g, d) = (d>>4)*64 + g*16 + (d&15)
// -> sLSTM cell computed in the GEMM epilogue from registers (no G scratch).
// SINGLE fp16 pass (fp32 accum); calibrated error ~4.1e-4 < 1e-3.
// GEMM = R11 best (2305us @ tensor 78.5%): 256 thr, 32x64 warp tiles, BK=64,
// 3-stage cp.async (CP_WAIT(1) slack), 2 CTAs/SM, stage order wait->sync->
// kk0 MMA->fill->kk1..3, GROUP=8. R10/R13 mainloop restructures both
// regressed ~55% -> mainloop frozen.
// R14: the three prep kernels merged into ONE launch (blockIdx.x-range
// dispatch) -> removes 2 launch boundaries + partial-wave tails.
// ============================================================================

#define BDIM 4096
#define DDIM 4096
#define KDIM 8192
#define NDIM 16384

#define BM 128
#define BN 128
#define BK 64
#define NITER (KDIM / BK)          // 128
#define TILEB (BM * BK * 2)        // 16384 bytes per operand tile
#define STAGEB (2 * TILEB)         // 32768 (A, B)
#define SMEMB (3 * STAGEB)         // 98304 -> 2 CTAs/SM

// prep grid partition
#define PX_BLKS 16384              // prep_x: 4,194,304 float4s / 256
#define PH_BLKS 4096               // prep_h: 64 x 64 tiles
#define PW_BLKS 32768              // prep_w: 64 x 64 x 8 tiles
#define PREP_BLKS (PX_BLKS + PH_BLKS + PW_BLKS)

// -------------------- scratch (module-scope, allowed) -----------------------
__device__ __align__(256) __half g_A[(size_t)BDIM * KDIM];
__device__ __align__(256) __half g_B[(size_t)NDIM * KDIM];

// -------------------- PTX helpers -------------------------------------------
__device__ __forceinline__ uint32_t smem_u32(const void* p) {
    uint32_t a;
    asm("{ .reg .u64 t; cvta.to.shared.u64 t, %1; cvt.u32.u64 %0, t; }"
        : "=r"(a) : "l"(p));
    return a;
}
__device__ __forceinline__ void cp_async16(uint32_t dst, const void* src) {
    asm volatile("cp.async.cg.shared.global [%0], [%1], 16;" :: "r"(dst), "l"(src) : "memory");
}
#define CP_COMMIT() asm volatile("cp.async.commit_group;" ::: "memory")
#define CP_WAIT(N)  asm volatile("cp.async.wait_group %0;" :: "n"(N) : "memory")

__device__ __forceinline__ void ldsm4(uint32_t& r0, uint32_t& r1, uint32_t& r2, uint32_t& r3,
                                      uint32_t addr) {
    asm volatile("ldmatrix.sync.aligned.m8n8.x4.shared.b16 {%0,%1,%2,%3}, [%4];"
                 : "=r"(r0), "=r"(r1), "=r"(r2), "=r"(r3) : "r"(addr));
}
__device__ __forceinline__ void mma16816(float* c, const uint32_t* a, const uint32_t* b) {
    asm volatile(
        "mma.sync.aligned.m16n8k16.row.col.f32.f16.f16.f32 "
        "{%0,%1,%2,%3}, {%4,%5,%6,%7}, {%8,%9}, {%0,%1,%2,%3};"
        : "+f"(c[0]), "+f"(c[1]), "+f"(c[2]), "+f"(c[3])
        : "r"(a[0]), "r"(a[1]), "r"(a[2]), "r"(a[3]), "r"(b[0]), "r"(b[1]));
}

// swizzled byte offset within one [128][64] fp16 tile (128B rows, 8 chunks).
__device__ __forceinline__ uint32_t sw_off(uint32_t row, uint32_t c16) {
    return row * 128u + (((c16 ^ row) & 7u) << 4);
}

// -------------------- merged prep kernel -------------------------------------
__global__ void __launch_bounds__(256) prep_all(
    const float* __restrict__ x, const float* __restrict__ h,
    const float* w0, const float* w1, const float* w2, const float* w3,
    const float* u0, const float* u1, const float* u2, const float* u3) {
    __shared__ float t[64][65];
    const int l = threadIdx.x;
    const int bid = blockIdx.x;

    if (bid < PX_BLKS) {
        // ---- prep_x: x (B, D) fp32 -> g_A[:, 0:4096] fp16 ----
        size_t gid = (size_t)bid * 256 + l;
        size_t i4 = gid * 4;
        int b = (int)(i4 >> 12), k = (int)(i4 & 4095);
        float4 v = reinterpret_cast<const float4*>(x)[gid];
        __half2* dst = reinterpret_cast<__half2*>(&g_A[(size_t)b * KDIM + k]);
        dst[0] = __floats2half2_rn(v.x, v.y);
        dst[1] = __floats2half2_rn(v.z, v.w);
    } else if (bid < PX_BLKS + PH_BLKS) {
        // ---- prep_h: h (D, B) fp32 -> g_A[b][4096 + r] = h[r][b] ----
        int tb = bid - PX_BLKS;
        int b0 = (tb & 63) * 64, r0 = (tb >> 6) * 64;
#pragma unroll
        for (int it = 0; it < 4; it++) {
            int idx = l + 256 * it;
            int row = idx >> 4;
            int c4 = idx & 15;
            float4 v = *reinterpret_cast<const float4*>(&h[(size_t)(r0 + row) * BDIM + b0 + c4 * 4]);
            t[row][c4 * 4 + 0] = v.x;
            t[row][c4 * 4 + 1] = v.y;
            t[row][c4 * 4 + 2] = v.z;
            t[row][c4 * 4 + 3] = v.w;
        }
        __syncthreads();
#pragma unroll
        for (int it = 0; it < 8; it++) {
            int idx = l + 256 * it;
            int brow = idx >> 5;
            int cp = idx & 31;
            __half2 v = __floats2half2_rn(t[2 * cp][brow], t[2 * cp + 1][brow]);
            size_t o = (size_t)(b0 + brow) * KDIM + 4096 + r0 + 2 * cp;
            *reinterpret_cast<__half2*>(&g_A[o]) = v;
        }
    } else {
        // ---- prep_w: 8 weight mats (k, d) fp32 -> g_B[pcol(g,d)][k'] fp16 ----
        int tb = bid - PX_BLKS - PH_BLKS;
        int bx = tb & 63, by = (tb >> 6) & 63, z = tb >> 12;
        const float* arr[8] = {w0, w1, w2, w3, u0, u1, u2, u3};
        const float* src = arr[z];
        int gate = z & 3, khalf = z >> 2;
        int d0 = bx * 64, k0 = by * 64;
#pragma unroll
        for (int it = 0; it < 4; it++) {
            int idx = l + 256 * it;
            int row = idx >> 4;
            int c4 = idx & 15;
            float4 v = *reinterpret_cast<const float4*>(&src[(size_t)(k0 + row) * DDIM + d0 + c4 * 4]);
            t[row][c4 * 4 + 0] = v.x;
            t[row][c4 * 4 + 1] = v.y;
            t[row][c4 * 4 + 2] = v.z;
            t[row][c4 * 4 + 3] = v.w;
        }
        __syncthreads();
#pragma unroll
        for (int it = 0; it < 8; it++) {
            int idx = l + 256 * it;
            int drow = idx >> 5;
            int cp = idx & 31;
            __half2 v = __floats2half2_rn(t[2 * cp][drow], t[2 * cp + 1][drow]);
            int d = d0 + drow;
            int prow = (d >> 4) * 64 + gate * 16 + (d & 15);   // gate interleave
            size_t o = (size_t)prow * KDIM + khalf * 4096 + k0 + 2 * cp;
            *reinterpret_cast<__half2*>(&g_B[o]) = v;
        }
    }
}

// -------------------- GEMM + fused cell kernel -------------------------------
// fill one 32KB stage with 256 threads: 8 cp.async/thread.
__device__ __forceinline__ void fill(uint32_t sdstA, uint32_t sdstB,
                                     const char*& pa, const char*& pb) {
    const size_t RSTEP = (size_t)32 * KDIM * 2;   // 32 rows in bytes
#pragma unroll
    for (int j = 0; j < 4; j++) {
        cp_async16(sdstA + 4096 * j, pa + (size_t)j * RSTEP);
        cp_async16(sdstB + 4096 * j, pb + (size_t)j * RSTEP);
    }
    pa += BK * 2;
    pb += BK * 2;
    CP_COMMIT();
}

__device__ __forceinline__ void ld_frags(
    int kk, int U, const uint32_t (&aA)[2][2], const uint32_t (&aB)[4][2], int dlt,
    uint32_t (&a)[2][4], uint32_t (&b)[8][2]) {
#pragma unroll
    for (int f = 0; f < 2; f++) {
        uint32_t ad = aA[f][kk & 1] + U * STAGEB + (kk >> 1) * dlt;
        ldsm4(a[f][0], a[f][1], a[f][2], a[f][3], ad);
    }
#pragma unroll
    for (int p = 0; p < 4; p++) {
        uint32_t bd = aB[p][kk & 1] + U * STAGEB + (kk >> 1) * dlt;
        uint32_t r0, r1, r2, r3;
        ldsm4(r0, r1, r2, r3, bd);
        b[p * 2 + 0][0] = r0; b[p * 2 + 0][1] = r2;
        b[p * 2 + 1][0] = r1; b[p * 2 + 1][1] = r3;
    }
}

// one pipeline step (R9 order): wait/sync -> kk0 ldsm+MMA -> fill (issues
// under tensor backpressure) -> kk1..3. Refills slot (U+2)%3.
template<int U, int WAITN, bool FILL>
__device__ __forceinline__ void gstep(
    uint32_t sb, uint32_t offA, uint32_t offB,
    const char*& pa, const char*& pb,
    const uint32_t (&aA)[2][2], const uint32_t (&aB)[4][2], int dlt,
    float (&acc)[2][8][4]) {
    CP_WAIT(WAITN);
    __syncthreads();

    uint32_t a[2][4];
    uint32_t b[8][2];
    ld_frags(0, U, aA, aB, dlt, a, b);
#pragma unroll
    for (int f = 0; f < 2; f++)
#pragma unroll
        for (int n = 0; n < 8; n++)
            mma16816(acc[f][n], a[f], b[n]);

    if (FILL) {
        const uint32_t fb = sb + ((U + 2) % 3) * STAGEB;
        fill(fb + offA, fb + offB, pa, pb);
    }

#pragma unroll
    for (int kk = 1; kk < 4; kk++) {
        ld_frags(kk, U, aA, aB, dlt, a, b);
#pragma unroll
        for (int f = 0; f < 2; f++)
#pragma unroll
            for (int n = 0; n < 8; n++)
                mma16816(acc[f][n], a[f], b[n]);
    }
}

__device__ __forceinline__ float cell1(float gi, float gf, float go, float gc,
                                       float cv, float mv, float nv,
                                       float& c_new, float& m_new, float& n_new) {
    m_new = fmaxf(gf + mv, gi);
    float i_p = expf(gi - m_new);
    float f_p = expf(gf);                 // faithful: +m_new - m_new cancels
    float o_t = 1.0f / (1.0f + expf(-go));
    float z_t = tanhf(gc);
    c_new = f_p * cv + i_p * z_t;
    n_new = f_p * nv + i_p;
    return o_t * (c_new / n_new);
}

__global__ void __launch_bounds__(256, 2) slstm_gemm(
    const float* __restrict__ cin, const float* __restrict__ min_,
    const float* __restrict__ nin,
    const float* __restrict__ bi, const float* __restrict__ bf,
    const float* __restrict__ bo, const float* __restrict__ bc,
    float* __restrict__ out) {
    extern __shared__ char smem[];
    uint32_t sb = smem_u32(smem);
    const int tid = threadIdx.x;
    const int wid = tid >> 5;
    const int lane = tid & 31;
    const int wm = wid >> 1;            // 0..3  (M warp, 32 rows)
    const int wn = wid & 1;             // 0..1  (N warp, 64 cols)

    // supertile rasterization for L2 reuse
    const int grid_m = BDIM / BM, grid_n = NDIM / BN;   // 32, 128
    const int GROUP = 8;
    int pid = blockIdx.x;
    int npg = GROUP * grid_n;
    int first_m = (pid / npg) * GROUP;
    int gs = min(grid_m - first_m, GROUP);
    int pig = pid % npg;
    int m0 = (first_m + (pig % gs)) * BM;
    int n0 = (pig / gs) * BN;

    // fill-side precompute
    const int frow = tid >> 3;          // 0..31
    const int fc = tid & 7;             // 16B chunk 0..7
    const uint32_t offA = sw_off(frow, fc);
    const uint32_t offB = offA + TILEB;
    const char* pa = (const char*)&g_A[(size_t)(m0 + frow) * KDIM] + fc * 16;
    const char* pb = (const char*)&g_B[(size_t)(n0 + frow) * KDIM] + fc * 16;

    // prologue: fill stages 0,1 into slots 0,1
    fill(sb + 0 * STAGEB + offA, sb + 0 * STAGEB + offB, pa, pb);
    fill(sb + 1 * STAGEB + offA, sb + 1 * STAGEB + offB, pa, pb);

    float acc[2][8][4];
#pragma unroll
    for (int f = 0; f < 2; f++)
#pragma unroll
        for (int n = 0; n < 8; n++)
#pragma unroll
            for (int v = 0; v < 4; v++) acc[f][n][v] = 0.0f;

    const int g = lane >> 3, lr = lane & 7;

    // hoisted swizzled ldmatrix addresses for slot 0, kk=0,1.
    uint32_t aA[2][2], aB[4][2];
#pragma unroll
    for (int f = 0; f < 2; f++)
#pragma unroll
        for (int kk = 0; kk < 2; kk++)
            aA[f][kk] = sb + 0 * TILEB +
                        sw_off(wm * 32 + f * 16 + lr + (g & 1) * 8, kk * 2 + (g >> 1));
#pragma unroll
    for (int p = 0; p < 4; p++)
#pragma unroll
        for (int kk = 0; kk < 2; kk++)
            aB[p][kk] = sb + 1 * TILEB +
                        sw_off(wn * 64 + p * 16 + lr + (g & 1) * 8, kk * 2 + (g >> 1));
    const int dlt = (lane & 4) ? -64 : 64;

    // main loop: stages 0..125 (42 x 3 slots), each fills stage s+2
    for (int s3 = 0; s3 < NITER - 2; s3 += 3) {
        gstep<0, 1, true>(sb, offA, offB, pa, pb, aA, aB, dlt, acc);
        gstep<1, 1, true>(sb, offA, offB, pa, pb, aA, aB, dlt, acc);
        gstep<2, 1, true>(sb, offA, offB, pa, pb, aA, aB, dlt, acc);
    }
    // tail: stages 126 (slot 0), 127 (slot 1)
    gstep<0, 1, false>(sb, offA, offB, pa, pb, aA, aB, dlt, acc);
    gstep<1, 0, false>(sb, offA, offB, pa, pb, aA, aB, dlt, acc);

    // ---------------- fused cell epilogue ----------------
    // Warp's 64 pcols = 16 features x 4 gates: gate g' at n-blocks 2g'+b,
    // feature d = dbase + b*8 + (lane&3)*2 (+0,+1).
    const size_t BD = (size_t)BDIM * DDIM;
    const int dbase = (n0 >> 2) + wn * 16;
    const int dth = dbase + (lane & 3) * 2;

    float2 bi2[2], bf2[2], bo2[2], bc2[2];
#pragma unroll
    for (int b = 0; b < 2; b++) {
        int d = dth + b * 8;
        bi2[b] = *reinterpret_cast<const float2*>(bi + d);
        bf2[b] = *reinterpret_cast<const float2*>(bf + d);
        bo2[b] = *reinterpret_cast<const float2*>(bo + d);
        bc2[b] = *reinterpret_cast<const float2*>(bc + d);
    }

    const size_t obase = (size_t)(m0 + wm * 32 + (lane >> 2)) * DDIM + dth;
#pragma unroll
    for (int f = 0; f < 2; f++) {
#pragma unroll
        for (int rr = 0; rr < 2; rr++) {        // rows +0, +8 within the frag
#pragma unroll
            for (int b = 0; b < 2; b++) {
                size_t o = obase + (size_t)(f * 16 + rr * 8) * DDIM + b * 8;
                float2 cv = *reinterpret_cast<const float2*>(cin + o);
                float2 mv = *reinterpret_cast<const float2*>(min_ + o);
                float2 nv = *reinterpret_cast<const float2*>(nin + o);

                float2 h2, c2, m2, n2;
                {
                    float gi = acc[f][0 + b][rr * 2 + 0] + bi2[b].x;
                    float gf = acc[f][2 + b][rr * 2 + 0] + bf2[b].x;
                    float go = acc[f][4 + b][rr * 2 + 0] + bo2[b].x;
                    float gc = acc[f][6 + b][rr * 2 + 0] + bc2[b].x;
                    h2.x = cell1(gi, gf, go, gc, cv.x, mv.x, nv.x, c2.x, m2.x, n2.x);
                }
                {
                    float gi = acc[f][0 + b][rr * 2 + 1] + bi2[b].y;
                    float gf = acc[f][2 + b][rr * 2 + 1] + bf2[b].y;
                    float go = acc[f][4 + b][rr * 2 + 1] + bo2[b].y;
                    float gc = acc[f][6 + b][rr * 2 + 1] + bc2[b].y;
                    h2.y = cell1(gi, gf, go, gc, cv.y, mv.y, nv.y, c2.y, m2.y, n2.y);
                }
                *reinterpret_cast<float2*>(out + 0 * BD + o) = h2;
                *reinterpret_cast<float2*>(out + 1 * BD + o) = c2;
                *reinterpret_cast<float2*>(out + 2 * BD + o) = m2;
                *reinterpret_cast<float2*>(out + 3 * BD + o) = n2;
            }
        }
    }
}

// -------------------- launcher ----------------------------------------------
extern "C" void kernel_launch(void* const* d_in, const int* in_sizes, int n_in,
                              void* d_out, int out_size) {
    (void)in_sizes; (void)n_in; (void)out_size;
    const float* x  = (const float*)d_in[0];
    const float* h  = (const float*)d_in[1];
    const float* c  = (const float*)d_in[2];
    const float* m  = (const float*)d_in[3];
    const float* n  = (const float*)d_in[4];
    const float* wi = (const float*)d_in[5];
    const float* wf = (const float*)d_in[6];
    const float* wo = (const float*)d_in[7];
    const float* wc = (const float*)d_in[8];
    const float* ui = (const float*)d_in[9];
    const float* uf = (const float*)d_in[10];
    const float* uo = (const float*)d_in[11];
    const float* uc = (const float*)d_in[12];
    const float* bi = (const float*)d_in[13];
    const float* bf = (const float*)d_in[14];
    const float* bo = (const float*)d_in[15];
    const float* bc = (const float*)d_in[16];

    cudaFuncSetAttribute(slstm_gemm, cudaFuncAttributeMaxDynamicSharedMemorySize, SMEMB);

    prep_all<<<PREP_BLKS, 256>>>(x, h, wi, wf, wo, wc, ui, uf, uo, uc);
    slstm_gemm<<<4096, 256, SMEMB>>>(c, m, n, bi, bf, bo, bc, (float*)d_out);
}